// round 6
// baseline (speedup 1.0000x reference)
#include <cuda_runtime.h>
#include <math.h>
#include <stdint.h>

#define Bsz 32
#define HW 65536          // H*W = 256*256
#define NPIX (Bsz * HW)
#define NBLK_MLP 592

// ---- scratch (no allocations allowed) ----
__device__ float g_e[NPIX];       // exp(score) at masked pixels (others stale/unused)
__device__ int   g_list[NPIX];    // compacted full pixel indices
__device__ int   g_total;
__device__ int   g_cnt[Bsz];
__device__ float g_sumE[Bsz];
__device__ float g_sumPE[Bsz];

#define FMA_F32X2(d, a, b, c) \
    asm("fma.rn.f32x2 %0, %1, %2, %3;" : "=l"(d) : "l"(a), "l"(b), "l"(c))
#define PACK_F32X2(out, lo, hi) \
    asm("mov.b64 %0, {%1, %2};" : "=l"(out) : "r"(lo), "r"(hi))
#define UNPACK_F32X2(lo, hi, in) \
    asm("mov.b64 {%0, %1}, %2;" : "=r"(lo), "=r"(hi) : "l"(in))

__global__ void k_init() {
    int t = threadIdx.x;
    if (t < Bsz) { g_cnt[t] = 0; g_sumE[t] = 0.0f; g_sumPE[t] = 0.0f; }
    if (t == 0) g_total = 0;
}

// Grid: 8192 blocks x 256 threads; block = one (b,row), so b is warp-uniform.
__global__ void k_compact(const int* __restrict__ zone,
                          const int* __restrict__ cats) {
    const int idx  = blockIdx.x * 256 + threadIdx.x;
    const int b    = idx >> 16;
    const int lane = threadIdx.x & 31;
    const bool m   = (zone[idx] == __ldg(&cats[b]));   // cats>=1 so zone>0 implied
    unsigned ball  = __ballot_sync(0xffffffffu, m);
    int pos = 0;
    if (lane == 0 && ball) {
        int n = __popc(ball);
        pos = atomicAdd(&g_total, n);
        atomicAdd(&g_cnt[b], n);
    }
    pos = __shfl_sync(0xffffffffu, pos, 0);
    if (m) g_list[pos + __popc(ball & ((1u << lane) - 1u))] = idx;
}

// Persistent MLP over compacted pixels. One pixel per thread; channels packed
// pairwise into f32x2; W1 pairs broadcast from SMEM via LDS.128.
// Two interleaved accumulator chains halve the serial FMA latency per k.
// 'offset' selects which grid-stride windows this launch covers (A/B split).
__global__ void __launch_bounds__(256) k_mlp(const float* __restrict__ feat,
                                             const float* __restrict__ pl,
                                             const float* __restrict__ W1,
                                             const float* __restrict__ b1,
                                             const float* __restrict__ W2,
                                             const float* __restrict__ b2p,
                                             int offset) {
    __shared__ __align__(16) float sW1[128 * 64];
    __shared__ float sB1[128], sW2[128];
    const int tid  = threadIdx.x;
    const int lane = tid & 31;

    for (int i = tid * 4; i < 128 * 64; i += 256 * 4)
        *(float4*)&sW1[i] = *(const float4*)&W1[i];
    if (tid < 128) { sB1[tid] = __ldg(&b1[tid]); sW2[tid] = __ldg(&W2[tid]); }
    __syncthreads();

    const int   total = g_total;
    const float b2    = __ldg(b2p);

    for (int base = offset + blockIdx.x * 256; base < total;
         base += 2 * NBLK_MLP * 256) {
        const int i  = base + tid;
        const int fi = (i < total) ? g_list[i] : -1;

        // gather 64 channels, packed as 32 f32x2 pairs (even, odd)
        uint64_t f2[32];
        if (fi >= 0) {
            const int bb = fi >> 16;
            const int p  = fi & 65535;
            const float* fp = feat + ((size_t)bb << 22) + p;   // b*64*65536
#pragma unroll
            for (int c = 0; c < 32; c++) {
                float fa = __ldg(fp + ((2 * c)     << 16));
                float fb = __ldg(fp + ((2 * c + 1) << 16));
                PACK_F32X2(f2[c], __float_as_uint(fa), __float_as_uint(fb));
            }
        } else {
#pragma unroll
            for (int c = 0; c < 32; c++) f2[c] = 0ull;
        }

        float score = b2;
#pragma unroll 2
        for (int k = 0; k < 128; k++) {
            uint64_t h2a, h2b;
            PACK_F32X2(h2a, __float_as_uint(sB1[k]), 0u);
            h2b = 0ull;
            const ulonglong2* w2v = (const ulonglong2*)&sW1[k * 64];
#pragma unroll
            for (int c = 0; c < 8; c++) {
                ulonglong2 wp0 = w2v[2 * c];           // LDS.128 broadcast
                ulonglong2 wp1 = w2v[2 * c + 1];
                FMA_F32X2(h2a, wp0.x, f2[4 * c + 0], h2a);
                FMA_F32X2(h2b, wp0.y, f2[4 * c + 1], h2b);
                FMA_F32X2(h2a, wp1.x, f2[4 * c + 2], h2a);
                FMA_F32X2(h2b, wp1.y, f2[4 * c + 3], h2b);
            }
            unsigned alo, ahi, blo, bhi;
            UNPACK_F32X2(alo, ahi, h2a);
            UNPACK_F32X2(blo, bhi, h2b);
            float h = (__uint_as_float(alo) + __uint_as_float(blo)) +
                      (__uint_as_float(ahi) + __uint_as_float(bhi));
            score = fmaf(sW2[k], fmaxf(h, 0.0f), score);
        }

        // per-batch sums with warp aggregation (warp is almost always batch-uniform)
        float e = 0.0f, pe = 0.0f;
        int bb = -1;
        if (fi >= 0) {
            e  = expf(score);    // |score| is O(1): no max-subtraction needed
            pe = e * __ldg(&pl[fi]);
            g_e[fi] = e;
            bb = fi >> 16;
        }
        unsigned act = __ballot_sync(0xffffffffu, fi >= 0);
        if (act) {
            int flead = __ffs(act) - 1;
            int b0 = __shfl_sync(0xffffffffu, bb, flead);
            bool uni = __all_sync(0xffffffffu, (fi < 0) || (bb == b0));
            if (uni) {
                float se = e, sp = pe;
#pragma unroll
                for (int off = 16; off; off >>= 1) {
                    se += __shfl_xor_sync(0xffffffffu, se, off);
                    sp += __shfl_xor_sync(0xffffffffu, sp, off);
                }
                if (lane == flead) {
                    atomicAdd(&g_sumE[b0],  se);
                    atomicAdd(&g_sumPE[b0], sp);
                }
            } else if (fi >= 0) {
                atomicAdd(&g_sumE[bb],  e);
                atomicAdd(&g_sumPE[bb], pe);
            }
        }
    }
}

// 4 pixels per thread; vector loads (aligned bases), scalar stores (out+1 is
// only 4B-aligned -> STG.128 would trap).
__global__ void k_maps(const int* __restrict__ zone,
                       const int* __restrict__ cats,
                       float* __restrict__ out_maps) {
    const int idx4 = (blockIdx.x * 256 + threadIdx.x) * 4;
    const int b    = idx4 >> 16;
    const int cat  = __ldg(&cats[b]);
    const bool has = g_cnt[b] > 0;
    const float inv = has ? (1.0f / g_sumE[b]) : 0.0f;
    int4   z = *(const int4*)&zone[idx4];
    float4 e = *(const float4*)&g_e[idx4];
    out_maps[idx4 + 0] = (has && z.x == cat) ? e.x * inv : 0.0f;
    out_maps[idx4 + 1] = (has && z.y == cat) ? e.y * inv : 0.0f;
    out_maps[idx4 + 2] = (has && z.z == cat) ? e.z * inv : 0.0f;
    out_maps[idx4 + 3] = (has && z.w == cat) ? e.w * inv : 0.0f;
}

__global__ void k_loss(const float* __restrict__ labels,
                       float* __restrict__ out, int write_loss) {
    const int t = threadIdx.x;   // 32 threads
    float x = 0.0f;
    if (g_cnt[t] > 0) x = g_sumPE[t] / g_sumE[t];
    const float y = labels[t];
    float term = fmaxf(x, 0.0f) - x * y + log1pf(expf(-fabsf(x)));
#pragma unroll
    for (int off = 16; off; off >>= 1)
        term += __shfl_xor_sync(0xffffffffu, term, off);
    if (t == 0 && write_loss) out[0] = term / 32.0f;
}

extern "C" void kernel_launch(void* const* d_in, const int* in_sizes, int n_in,
                              void* d_out, int out_size) {
    const float* pl     = (const float*)d_in[0];  // (B,1,H,W)
    const float* feat   = (const float*)d_in[1];  // (B,C,H,W)
    const int*   zone   = (const int*)  d_in[2];  // (B,H,W)
    const int*   cats   = (const int*)  d_in[3];  // (B,)
    const float* labels = (const float*)d_in[4];  // (B,)
    const float* W1     = (const float*)d_in[5];  // (128,64)
    const float* b1     = (const float*)d_in[6];  // (128,)
    const float* W2     = (const float*)d_in[7];  // (128,)
    const float* b2     = (const float*)d_in[8];  // ()
    float* out = (float*)d_out;

    const int nmap = NPIX;
    int map_off = out_size - nmap;
    if (map_off < 0) map_off = 0;

    k_init<<<1, 32>>>();
    k_compact<<<NPIX / 256, 256>>>(zone, cats);
    // A/B split: disjoint grid-stride windows; B sits at launch position 4 so
    // the fixed ncu capture slot (-s 5 -c 1) profiles the hot MLP kernel.
    k_mlp<<<NBLK_MLP, 256>>>(feat, pl, W1, b1, W2, b2, 0);
    k_mlp<<<NBLK_MLP, 256>>>(feat, pl, W1, b1, W2, b2, NBLK_MLP * 256);
    k_maps<<<NPIX / 1024, 256>>>(zone, cats, out + map_off);
    k_loss<<<1, 32>>>(labels, out, map_off >= 1 ? 1 : 0);
}

// round 7
// speedup vs baseline: 1.0856x; 1.0856x over previous
#include <cuda_runtime.h>
#include <math.h>
#include <stdint.h>

#define Bsz 32
#define HW 65536          // H*W = 256*256
#define NPIX (Bsz * HW)
#define NBLK_MLP 444      // 3 blocks/SM * 148 SMs
#define TPB_MLP 128

// ---- scratch (no allocations allowed) ----
__device__ float g_e[NPIX];       // exp(score) at masked pixels (others stale/unused)
__device__ int   g_list[NPIX];    // compacted full pixel indices
__device__ int   g_total;
__device__ int   g_cnt[Bsz];
__device__ float g_sumE[Bsz];
__device__ float g_sumPE[Bsz];

#define FMA_F32X2(d, a, b, c) \
    asm("fma.rn.f32x2 %0, %1, %2, %3;" : "=l"(d) : "l"(a), "l"(b), "l"(c))
#define PACK_F32X2(out, lo, hi) \
    asm("mov.b64 %0, {%1, %2};" : "=l"(out) : "r"(lo), "r"(hi))
#define UNPACK_F32X2(lo, hi, in) \
    asm("mov.b64 {%0, %1}, %2;" : "=r"(lo), "=r"(hi) : "l"(in))

__global__ void k_init() {
    int t = threadIdx.x;
    if (t < Bsz) { g_cnt[t] = 0; g_sumE[t] = 0.0f; g_sumPE[t] = 0.0f; }
    if (t == 0) g_total = 0;
}

__global__ void k_nop() {}   // launch-order pad so ncu's fixed slot lands on k_mlp

// Grid: 8192 blocks x 256 threads; block = one (b,row), so b is warp-uniform.
__global__ void k_compact(const int* __restrict__ zone,
                          const int* __restrict__ cats) {
    const int idx  = blockIdx.x * 256 + threadIdx.x;
    const int b    = idx >> 16;
    const int lane = threadIdx.x & 31;
    const bool m   = (zone[idx] == __ldg(&cats[b]));   // cats>=1 so zone>0 implied
    unsigned ball  = __ballot_sync(0xffffffffu, m);
    int pos = 0;
    if (lane == 0 && ball) {
        int n = __popc(ball);
        pos = atomicAdd(&g_total, n);
        atomicAdd(&g_cnt[b], n);
    }
    pos = __shfl_sync(0xffffffffu, pos, 0);
    if (m) g_list[pos + __popc(ball & ((1u << lane) - 1u))] = idx;
}

// Persistent MLP over compacted pixels. One pixel per thread; channels packed
// pairwise into f32x2. Weights stream from SMEM with an explicit half-k
// double-buffered prefetch (8x LDS.128 in flight one half ahead), so FFMA2s
// never wait on the 29-cycle LDS latency.
__global__ void __launch_bounds__(TPB_MLP, 3)
k_mlp(const float* __restrict__ feat,
      const float* __restrict__ pl,
      const float* __restrict__ W1,
      const float* __restrict__ b1,
      const float* __restrict__ W2,
      const float* __restrict__ b2p) {
    __shared__ __align__(16) float sW1[128 * 64];
    __shared__ float sB1[128], sW2[128];
    const int tid  = threadIdx.x;
    const int lane = tid & 31;

    for (int i = tid * 4; i < 128 * 64; i += TPB_MLP * 4)
        *(float4*)&sW1[i] = *(const float4*)&W1[i];
    sB1[tid] = __ldg(&b1[tid]);
    sW2[tid] = __ldg(&W2[tid]);
    __syncthreads();

    const int   total = g_total;
    const float b2    = __ldg(b2p);
    const ulonglong2* wv = (const ulonglong2*)sW1;   // 16 per k (64 floats)

    for (int base = blockIdx.x * TPB_MLP; base < total; base += NBLK_MLP * TPB_MLP) {
        const int i  = base + tid;
        const int fi = (i < total) ? g_list[i] : -1;

        // gather 64 channels, packed as 32 f32x2 pairs (even, odd)
        uint64_t f2[32];
        if (fi >= 0) {
            const int bb = fi >> 16;
            const int p  = fi & 65535;
            const float* fp = feat + ((size_t)bb << 22) + p;   // b*64*65536
#pragma unroll
            for (int c = 0; c < 32; c++) {
                float fa = __ldg(fp + ((2 * c)     << 16));
                float fb = __ldg(fp + ((2 * c + 1) << 16));
                PACK_F32X2(f2[c], __float_as_uint(fa), __float_as_uint(fb));
            }
        } else {
#pragma unroll
            for (int c = 0; c < 32; c++) f2[c] = 0ull;
        }

        float score = b2;
        ulonglong2 wA[8], wB[8];
        // preload k=0, half 0
#pragma unroll
        for (int j = 0; j < 8; j++) wA[j] = wv[j];

#pragma unroll 2
        for (int k = 0; k < 128; k++) {
            uint64_t h2a, h2b;
            PACK_F32X2(h2a, __float_as_uint(sB1[k]), 0u);
            h2b = 0ull;
            // prefetch half 1 of k
#pragma unroll
            for (int j = 0; j < 8; j++) wB[j] = wv[k * 16 + 8 + j];
            // compute half 0 from wA (16 FFMA2, two chains)
#pragma unroll
            for (int j = 0; j < 8; j++) {
                FMA_F32X2(h2a, wA[j].x, f2[2 * j],     h2a);
                FMA_F32X2(h2b, wA[j].y, f2[2 * j + 1], h2b);
            }
            // prefetch half 0 of k+1 (wraps harmlessly at k=127)
            const int kn = (k + 1) & 127;
#pragma unroll
            for (int j = 0; j < 8; j++) wA[j] = wv[kn * 16 + j];
            // compute half 1 from wB
#pragma unroll
            for (int j = 0; j < 8; j++) {
                FMA_F32X2(h2a, wB[j].x, f2[16 + 2 * j], h2a);
                FMA_F32X2(h2b, wB[j].y, f2[17 + 2 * j], h2b);
            }
            unsigned alo, ahi, blo, bhi;
            UNPACK_F32X2(alo, ahi, h2a);
            UNPACK_F32X2(blo, bhi, h2b);
            float h = (__uint_as_float(alo) + __uint_as_float(blo)) +
                      (__uint_as_float(ahi) + __uint_as_float(bhi));
            score = fmaf(sW2[k], fmaxf(h, 0.0f), score);
        }

        // per-batch sums with warp aggregation (warp is almost always batch-uniform)
        float e = 0.0f, pe = 0.0f;
        int bb = -1;
        if (fi >= 0) {
            e  = expf(score);    // |score| is O(1): no max-subtraction needed
            pe = e * __ldg(&pl[fi]);
            g_e[fi] = e;
            bb = fi >> 16;
        }
        unsigned act = __ballot_sync(0xffffffffu, fi >= 0);
        if (act) {
            int flead = __ffs(act) - 1;
            int b0 = __shfl_sync(0xffffffffu, bb, flead);
            bool uni = __all_sync(0xffffffffu, (fi < 0) || (bb == b0));
            if (uni) {
                float se = e, sp = pe;
#pragma unroll
                for (int off = 16; off; off >>= 1) {
                    se += __shfl_xor_sync(0xffffffffu, se, off);
                    sp += __shfl_xor_sync(0xffffffffu, sp, off);
                }
                if (lane == flead) {
                    atomicAdd(&g_sumE[b0],  se);
                    atomicAdd(&g_sumPE[b0], sp);
                }
            } else if (fi >= 0) {
                atomicAdd(&g_sumE[bb],  e);
                atomicAdd(&g_sumPE[bb], pe);
            }
        }
    }
}

// 4 pixels per thread; vector loads (aligned bases), scalar stores (out+1 is
// only 4B-aligned -> STG.128 would trap).
__global__ void k_maps(const int* __restrict__ zone,
                       const int* __restrict__ cats,
                       float* __restrict__ out_maps) {
    const int idx4 = (blockIdx.x * 256 + threadIdx.x) * 4;
    const int b    = idx4 >> 16;
    const int cat  = __ldg(&cats[b]);
    const bool has = g_cnt[b] > 0;
    const float inv = has ? (1.0f / g_sumE[b]) : 0.0f;
    int4   z = *(const int4*)&zone[idx4];
    float4 e = *(const float4*)&g_e[idx4];
    out_maps[idx4 + 0] = (has && z.x == cat) ? e.x * inv : 0.0f;
    out_maps[idx4 + 1] = (has && z.y == cat) ? e.y * inv : 0.0f;
    out_maps[idx4 + 2] = (has && z.z == cat) ? e.z * inv : 0.0f;
    out_maps[idx4 + 3] = (has && z.w == cat) ? e.w * inv : 0.0f;
}

__global__ void k_loss(const float* __restrict__ labels,
                       float* __restrict__ out, int write_loss) {
    const int t = threadIdx.x;   // 32 threads
    float x = 0.0f;
    if (g_cnt[t] > 0) x = g_sumPE[t] / g_sumE[t];
    const float y = labels[t];
    float term = fmaxf(x, 0.0f) - x * y + log1pf(expf(-fabsf(x)));
#pragma unroll
    for (int off = 16; off; off >>= 1)
        term += __shfl_xor_sync(0xffffffffu, term, off);
    if (t == 0 && write_loss) out[0] = term / 32.0f;
}

extern "C" void kernel_launch(void* const* d_in, const int* in_sizes, int n_in,
                              void* d_out, int out_size) {
    const float* pl     = (const float*)d_in[0];  // (B,1,H,W)
    const float* feat   = (const float*)d_in[1];  // (B,C,H,W)
    const int*   zone   = (const int*)  d_in[2];  // (B,H,W)
    const int*   cats   = (const int*)  d_in[3];  // (B,)
    const float* labels = (const float*)d_in[4];  // (B,)
    const float* W1     = (const float*)d_in[5];  // (128,64)
    const float* b1     = (const float*)d_in[6];  // (128,)
    const float* W2     = (const float*)d_in[7];  // (128,)
    const float* b2     = (const float*)d_in[8];  // ()
    float* out = (float*)d_out;

    const int nmap = NPIX;
    int map_off = out_size - nmap;
    if (map_off < 0) map_off = 0;

    k_init<<<1, 32>>>();
    k_compact<<<NPIX / 256, 256>>>(zone, cats);
    k_nop<<<1, 32>>>();   // pad: keeps k_mlp in the profiled (4th) launch slot
    k_mlp<<<NBLK_MLP, TPB_MLP>>>(feat, pl, W1, b1, W2, b2);
    k_maps<<<NPIX / 1024, 256>>>(zone, cats, out + map_off);
    k_loss<<<1, 32>>>(labels, out, map_off >= 1 ? 1 : 0);
}